// round 2
// baseline (speedup 1.0000x reference)
#include <cuda_runtime.h>
#include <math_constants.h>

// LSS view transformer, GB300 sm_103a.
// img_feat:     (1, 6, 128, 32, 88) f32   d_in[0]
// depth_logits: (1, 6,  40, 32, 88) f32   d_in[1]
// rots/trans/intrins: unused by the reference's index math (pure constants)
// out:          (1, 128, 125, 125) f32
//
// Per-pixel block: softmax over depth (6 cams), compute static voxel index
// per depth bin (monotone in d -> runs of equal voxel), sum probs per run per
// cam, combine cams, one global RED.F32 per (run, channel).

#define D_N 40
#define H_N 32
#define W_N 88
#define CAM_N 6
#define C_N 128
#define BEV 125
#define NVOX (BEV * BEV)

__global__ __launch_bounds__(256, 8) void lss_scatter_kernel(
    const float* __restrict__ img_feat,
    const float* __restrict__ depth_logits,
    float* __restrict__ out)
{
    __shared__ float s_p[CAM_N][D_N];     // logits -> exp -> probs (in place)
    __shared__ float s_mx[CAM_N];
    __shared__ float s_inv[CAM_N];
    __shared__ int   s_idx[D_N];
    __shared__ int   s_run_vox[D_N];
    __shared__ int   s_run_lo[D_N + 1];
    __shared__ float s_wsum[D_N][CAM_N];
    __shared__ int   s_nr;

    const int p   = blockIdx.x;           // pixel id: h*88 + w
    const int h   = p / W_N;
    const int w   = p - h * W_N;
    const int tid = threadIdx.x;
    const int cam = tid / D_N;
    const int d   = tid - cam * D_N;

    // ---- load depth logits for all 6 cameras of this pixel ----
    if (tid < CAM_N * D_N)
        s_p[cam][d] = depth_logits[((cam * D_N + d) * H_N + h) * W_N + w];
    __syncthreads();

    // ---- softmax over depth per camera ----
    if (tid < CAM_N) {
        float m = -CUDART_INF_F;
        #pragma unroll
        for (int i = 0; i < D_N; ++i) m = fmaxf(m, s_p[tid][i]);
        s_mx[tid] = m;
    }
    __syncthreads();
    if (tid < CAM_N * D_N)
        s_p[cam][d] = __expf(s_p[cam][d] - s_mx[cam]);
    __syncthreads();
    if (tid < CAM_N) {
        float s = 0.0f;
        #pragma unroll
        for (int i = 0; i < D_N; ++i) s += s_p[tid][i];
        s_inv[tid] = 1.0f / s;
    }
    __syncthreads();
    if (tid < CAM_N * D_N)
        s_p[cam][d] *= s_inv[cam];

    // ---- static voxel index per depth bin (replicates reference fp32 ops,
    //      no FMA contraction: round each op like unfused XLA) ----
    if (tid < D_N) {
        float dv = (float)(tid + 2);                 // depth value 2..41
        float xd = __fmul_rn((float)w, dv);          // exact (small ints)
        float yd = __fmul_rn((float)h, dv);
        // gx = xd/3567*100 - 50 ; gy = yd/1271*100 - 50
        float gx = __fadd_rn(__fmul_rn(__fdiv_rn(xd, 3567.0f), 100.0f), -50.0f);
        float gy = __fadd_rn(__fmul_rn(__fdiv_rn(yd, 1271.0f), 100.0f), -50.0f);
        int ix = (int)__fdiv_rn(__fadd_rn(gx, 50.0f), 0.8f);
        int iy = (int)__fdiv_rn(__fadd_rn(gy, 50.0f), 0.8f);
        // iz = (d+2+10)/20 >= 0 always; ix,iy >= 0 always (gx+50 >= 0)
        bool valid = (ix >= 0) && (ix < BEV) && (iy >= 0) && (iy < BEV);
        s_idx[tid] = valid ? (iy * BEV + ix) : -1;
    }
    __syncthreads();

    // ---- compact equal-voxel runs (validity is a prefix in d: ix,iy
    //      are monotone nondecreasing in d) ----
    if (tid == 0) {
        int nr = 0, prev = -2, end = D_N;
        for (int i = 0; i < D_N; ++i) {
            int v = s_idx[i];
            if (v < 0) { end = i; break; }
            if (v != prev) { s_run_vox[nr] = v; s_run_lo[nr] = i; ++nr; prev = v; }
        }
        s_run_lo[nr] = end;
        s_nr = nr;
    }
    __syncthreads();

    const int nr = s_nr;

    // ---- per-run, per-camera probability sum ----
    if (tid < nr * CAM_N) {
        int r = tid / CAM_N, cm = tid - r * CAM_N;
        float s = 0.0f;
        int lo = s_run_lo[r], hi = s_run_lo[r + 1];
        for (int i = lo; i < hi; ++i) s += s_p[cm][i];
        s_wsum[r][cm] = s;
    }
    __syncthreads();

    // ---- scatter: combine 6 cameras into one value per (run, channel),
    //      one RED.F32 per value. Threads 0..127 take even runs, 128..255 odd.
    const int c  = tid & (C_N - 1);
    const int r0 = tid >> 7;

    const int fbase = (c * H_N + h) * W_N + w;
    float f0 = img_feat[fbase + 0 * C_N * H_N * W_N];
    float f1 = img_feat[fbase + 1 * C_N * H_N * W_N];
    float f2 = img_feat[fbase + 2 * C_N * H_N * W_N];
    float f3 = img_feat[fbase + 3 * C_N * H_N * W_N];
    float f4 = img_feat[fbase + 4 * C_N * H_N * W_N];
    float f5 = img_feat[fbase + 5 * C_N * H_N * W_N];

    float* out_c = out + (size_t)c * NVOX;
    for (int r = r0; r < nr; r += 2) {
        float val = s_wsum[r][0] * f0 + s_wsum[r][1] * f1 + s_wsum[r][2] * f2
                  + s_wsum[r][3] * f3 + s_wsum[r][4] * f4 + s_wsum[r][5] * f5;
        atomicAdd(out_c + s_run_vox[r], val);
    }
}

extern "C" void kernel_launch(void* const* d_in, const int* in_sizes, int n_in,
                              void* d_out, int out_size)
{
    const float* img_feat     = (const float*)d_in[0];
    const float* depth_logits = (const float*)d_in[1];
    float* out = (float*)d_out;

    // Output is poisoned; zero it (memset node is graph-capturable).
    cudaMemsetAsync(out, 0, (size_t)out_size * sizeof(float), 0);

    lss_scatter_kernel<<<H_N * W_N, 256>>>(img_feat, depth_logits, out);
}